// round 1
// baseline (speedup 1.0000x reference)
#include <cuda_runtime.h>
#include <math.h>

#define N_NODES 80000
#define N_EDGES 1280000
#define IN_C    128
#define HID_C   64
#define OUT_C   40

#define SCAN_CHUNK 1024
#define NCHUNK ((N_NODES + SCAN_CHUNK - 1) / SCAN_CHUNK)   // 79

// ---------------- static device scratch (no allocations allowed) ----------
__device__ float g_h1[N_NODES * HID_C];     // x @ W1
__device__ float g_a1[N_NODES * HID_C];     // relu(aggregate(h1))
__device__ float g_h2[N_NODES * OUT_C];     // a1 @ W2
__device__ int   g_deg[N_NODES];
__device__ int   g_off[N_NODES + 1];
__device__ int   g_cur[N_NODES];
__device__ int   g_csr_src[N_EDGES];
__device__ int   g_bsum[NCHUNK];
__device__ int   g_bpre[NCHUNK];

// ---------------- CSR build -----------------------------------------------

__global__ void k_zero_deg() {
    int i = blockIdx.x * blockDim.x + threadIdx.x;
    if (i < N_NODES) g_deg[i] = 0;
}

__global__ void k_hist(const int* __restrict__ ei) {
    int e = blockIdx.x * blockDim.x + threadIdx.x;
    if (e < N_EDGES) {
        int dst = ei[N_EDGES + e];
        atomicAdd(&g_deg[dst], 1);
    }
}

// block-wide exclusive scan (blockDim multiple of 32, <=1024)
__device__ __forceinline__ int block_scan_excl(int v, int* smem32) {
    int lane = threadIdx.x & 31;
    int wid  = threadIdx.x >> 5;
    int nw   = blockDim.x >> 5;
    int s = v;
#pragma unroll
    for (int d = 1; d < 32; d <<= 1) {
        int t = __shfl_up_sync(0xffffffffu, s, d);
        if (lane >= d) s += t;
    }
    if (lane == 31) smem32[wid] = s;
    __syncthreads();
    if (wid == 0) {
        int ws = (lane < nw) ? smem32[lane] : 0;
        int ss = ws;
#pragma unroll
        for (int d = 1; d < 32; d <<= 1) {
            int t = __shfl_up_sync(0xffffffffu, ss, d);
            if (lane >= d) ss += t;
        }
        smem32[lane] = ss - ws;   // exclusive warp offset
    }
    __syncthreads();
    return smem32[wid] + (s - v);
}

__global__ void k_scan_partial() {   // NCHUNK blocks x 1024
    __shared__ int sm[32];
    int i = blockIdx.x * SCAN_CHUNK + threadIdx.x;
    int v = (i < N_NODES) ? g_deg[i] : 0;
    // block reduce (sum)
    int lane = threadIdx.x & 31, wid = threadIdx.x >> 5;
    int s = v;
#pragma unroll
    for (int d = 16; d > 0; d >>= 1) s += __shfl_xor_sync(0xffffffffu, s, d);
    if (lane == 0) sm[wid] = s;
    __syncthreads();
    if (wid == 0) {
        int t = (lane < (blockDim.x >> 5)) ? sm[lane] : 0;
#pragma unroll
        for (int d = 16; d > 0; d >>= 1) t += __shfl_xor_sync(0xffffffffu, t, d);
        if (lane == 0) g_bsum[blockIdx.x] = t;
    }
}

__global__ void k_scan_blocksums() {  // 1 block x 128
    __shared__ int sm[32];
    int t = threadIdx.x;
    int v = (t < NCHUNK) ? g_bsum[t] : 0;
    int ex = block_scan_excl(v, sm);
    if (t < NCHUNK) g_bpre[t] = ex;
    if (t == 0) g_off[N_NODES] = N_EDGES;
}

__global__ void k_scan_final() {     // NCHUNK blocks x 1024
    __shared__ int sm[32];
    int i = blockIdx.x * SCAN_CHUNK + threadIdx.x;
    int v = (i < N_NODES) ? g_deg[i] : 0;
    int ex = block_scan_excl(v, sm) + g_bpre[blockIdx.x];
    if (i < N_NODES) {
        g_off[i] = ex;
        g_cur[i] = ex;
    }
}

__global__ void k_fill(const int* __restrict__ ei) {
    int e = blockIdx.x * blockDim.x + threadIdx.x;
    if (e < N_EDGES) {
        int src = ei[e];
        int dst = ei[N_EDGES + e];
        int p = atomicAdd(&g_cur[dst], 1);
        g_csr_src[p] = src;
    }
}

// ---------------- GEMM 1: h1 = x @ W1  [80000,128]x[128,64] ---------------

__global__ __launch_bounds__(256) void k_gemm1(const float* __restrict__ x,
                                               const float* __restrict__ W1) {
    __shared__ float Ws[IN_C * HID_C];   // 32 KB
    for (int i = threadIdx.x; i < IN_C * HID_C; i += blockDim.x) Ws[i] = W1[i];
    __syncthreads();

    int v = blockIdx.x * blockDim.x + threadIdx.x;
    if (v >= N_NODES) return;

    float acc[HID_C];
#pragma unroll
    for (int j = 0; j < HID_C; j++) acc[j] = 0.f;

    const float4* xr = (const float4*)(x + (size_t)v * IN_C);
#pragma unroll 2
    for (int k4 = 0; k4 < IN_C / 4; k4++) {
        float4 xv = xr[k4];
        int kb = k4 * 4;
#pragma unroll
        for (int c = 0; c < 4; c++) {
            float xc = (c == 0) ? xv.x : (c == 1) ? xv.y : (c == 2) ? xv.z : xv.w;
            const float4* wr = (const float4*)(Ws + (kb + c) * HID_C);
#pragma unroll
            for (int j4 = 0; j4 < HID_C / 4; j4++) {
                float4 w = wr[j4];
                acc[4 * j4 + 0] += xc * w.x;
                acc[4 * j4 + 1] += xc * w.y;
                acc[4 * j4 + 2] += xc * w.z;
                acc[4 * j4 + 3] += xc * w.w;
            }
        }
    }
    float4* o = (float4*)(g_h1 + (size_t)v * HID_C);
#pragma unroll
    for (int j4 = 0; j4 < HID_C / 4; j4++)
        o[j4] = make_float4(acc[4*j4], acc[4*j4+1], acc[4*j4+2], acc[4*j4+3]);
}

// ---------------- SpMM 1 + relu: a1[v] = relu(sum_{s in N(v)} h1[s]) ------

__global__ void k_spmm1() {
    int gw = (blockIdx.x * blockDim.x + threadIdx.x) >> 5;
    if (gw >= N_NODES) return;
    int lane = threadIdx.x & 31;
    int beg = g_off[gw], end = g_off[gw + 1];

    const float2* h1v = (const float2*)g_h1;
    float2 acc = make_float2(0.f, 0.f);
    for (int idx = beg; idx < end; idx++) {
        int s = __ldg(&g_csr_src[idx]);          // uniform across warp
        float2 hv = __ldg(&h1v[(size_t)s * (HID_C / 2) + lane]);
        acc.x += hv.x;
        acc.y += hv.y;
    }
    ((float2*)g_a1)[(size_t)gw * (HID_C / 2) + lane] =
        make_float2(fmaxf(acc.x, 0.f), fmaxf(acc.y, 0.f));
}

// ---------------- GEMM 2: h2 = a1 @ W2  [80000,64]x[64,40] ----------------

__global__ __launch_bounds__(256) void k_gemm2(const float* __restrict__ W2) {
    __shared__ float Ws[HID_C * OUT_C];  // 10.25 KB
    for (int i = threadIdx.x; i < HID_C * OUT_C; i += blockDim.x) Ws[i] = W2[i];
    __syncthreads();

    int v = blockIdx.x * blockDim.x + threadIdx.x;
    if (v >= N_NODES) return;

    float acc[OUT_C];
#pragma unroll
    for (int j = 0; j < OUT_C; j++) acc[j] = 0.f;

    const float4* ar = (const float4*)(g_a1 + (size_t)v * HID_C);
#pragma unroll 2
    for (int k4 = 0; k4 < HID_C / 4; k4++) {
        float4 av = ar[k4];
        int kb = k4 * 4;
#pragma unroll
        for (int c = 0; c < 4; c++) {
            float ac = (c == 0) ? av.x : (c == 1) ? av.y : (c == 2) ? av.z : av.w;
            const float4* wr = (const float4*)(Ws + (kb + c) * OUT_C);
#pragma unroll
            for (int j4 = 0; j4 < OUT_C / 4; j4++) {
                float4 w = wr[j4];
                acc[4 * j4 + 0] += ac * w.x;
                acc[4 * j4 + 1] += ac * w.y;
                acc[4 * j4 + 2] += ac * w.z;
                acc[4 * j4 + 3] += ac * w.w;
            }
        }
    }
    float4* o = (float4*)(g_h2 + (size_t)v * OUT_C);
#pragma unroll
    for (int j4 = 0; j4 < OUT_C / 4; j4++)
        o[j4] = make_float4(acc[4*j4], acc[4*j4+1], acc[4*j4+2], acc[4*j4+3]);
}

// ---------------- SpMM 2 + log_softmax ------------------------------------
// warp per node; lanes 0..19 each hold 2 of the 40 output columns.

__global__ void k_spmm2_lsm(float* __restrict__ out) {
    int gw = (blockIdx.x * blockDim.x + threadIdx.x) >> 5;
    if (gw >= N_NODES) return;
    int lane = threadIdx.x & 31;
    int beg = g_off[gw], end = g_off[gw + 1];

    const float2* h2v = (const float2*)g_h2;
    float2 acc = make_float2(0.f, 0.f);
    bool active = lane < (OUT_C / 2);
    for (int idx = beg; idx < end; idx++) {
        int s = __ldg(&g_csr_src[idx]);
        if (active) {
            float2 hv = __ldg(&h2v[(size_t)s * (OUT_C / 2) + lane]);
            acc.x += hv.x;
            acc.y += hv.y;
        }
    }
    // max over 40 values
    float m = active ? fmaxf(acc.x, acc.y) : -INFINITY;
#pragma unroll
    for (int d = 16; d > 0; d >>= 1) m = fmaxf(m, __shfl_xor_sync(0xffffffffu, m, d));
    // log-sum-exp
    float sum = active ? (expf(acc.x - m) + expf(acc.y - m)) : 0.f;
#pragma unroll
    for (int d = 16; d > 0; d >>= 1) sum += __shfl_xor_sync(0xffffffffu, sum, d);
    float lse = logf(sum);
    if (active) {
        ((float2*)out)[(size_t)gw * (OUT_C / 2) + lane] =
            make_float2(acc.x - m - lse, acc.y - m - lse);
    }
}

// ---------------- launch ---------------------------------------------------

extern "C" void kernel_launch(void* const* d_in, const int* in_sizes, int n_in,
                              void* d_out, int out_size) {
    const float* x  = (const float*)d_in[0];     // [80000,128]
    const int*   ei = (const int*)d_in[1];       // [2,1280000]
    const float* W1 = (const float*)d_in[2];     // [128,64]
    const float* W2 = (const float*)d_in[3];     // [64,40]
    float* out = (float*)d_out;                  // [80000,40]

    const int TB = 256;

    // CSR build (int atomics only)
    k_zero_deg<<<(N_NODES + TB - 1) / TB, TB>>>();
    k_hist<<<(N_EDGES + TB - 1) / TB, TB>>>(ei);
    k_scan_partial<<<NCHUNK, SCAN_CHUNK>>>();
    k_scan_blocksums<<<1, 128>>>();
    k_scan_final<<<NCHUNK, SCAN_CHUNK>>>();
    k_fill<<<(N_EDGES + TB - 1) / TB, TB>>>(ei);

    // layer 1
    k_gemm1<<<(N_NODES + TB - 1) / TB, TB>>>(x, W1);
    k_spmm1<<<(N_NODES * 32 + TB - 1) / TB, TB>>>();

    // layer 2 + log_softmax
    k_gemm2<<<(N_NODES + TB - 1) / TB, TB>>>(W2);
    k_spmm2_lsm<<<(N_NODES * 32 + TB - 1) / TB, TB>>>(out);
}